// round 8
// baseline (speedup 1.0000x reference)
#include <cuda_runtime.h>

// Kalman filter, fused-congruence formulation, 4 threads per batch.
// B=4096, T=200, S=8, M=2. Thread r of a batch owns state rows {2r, 2r+1}.
// 8 batches per 32-thread warp/block, 512 blocks (~3.5 warps/SM, 1/SMSP).
// Each thread reads the broadcast P / Z matrices ONCE and produces TWO output
// rows, halving the dominant SMEM-crossbar traffic vs the 8-thread layout.
//
// Per step:
//   HP  = H P  (own register rows of P; P symmetric)
//   S   = HP H^T + R ; W = S^{-1} HP ; K = W^T
//   C   = F K ; Z = F - C H (registers)
//   mean' = fr.mn + C.resid
//   P'  = Z P Z^T + C R C^T + Q   (two broadcast matmuls, each serving 2 rows)

namespace {
constexpr int Bb  = 4096;
constexpr int Tt  = 200;
constexpr int BPW = 8;     // batches per warp/block
constexpr int WSF = 196;   // workspace stride (mod 32 == 4, 16B-aligned)
}

__global__ __launch_bounds__(32)
void kalman_kernel(const float* __restrict__ gy,      // [B,T,2]
                   const float* __restrict__ gF,      // [B,T,8,8]
                   const float* __restrict__ gH,      // [B,T,2,8]
                   const float* __restrict__ gQ,      // [8,8]
                   const float* __restrict__ gR,      // [2,2]
                   const float* __restrict__ gMean0,  // [B,8]
                   const float* __restrict__ gCov0,   // [8,8]
                   float* __restrict__ oMean,         // [B,T,8]
                   float* __restrict__ oCov)          // [B,T,8,8]
{
    __shared__ __align__(16) float sw[BPW * WSF];
    const int lane = threadIdx.x;
    const int lb   = lane >> 2;        // batch within warp
    const int r    = lane & 3;
    const int a    = 2 * r;            // first owned state row (a, a+1)
    const int b    = blockIdx.x * BPW + lb;

    float* wsp   = sw + lb * WSF;
    float* sP    = wsp;          // 64: covariance (predicted)
    float* sZ    = wsp + 64;     // 64: Z = F(I-KH)
    float* sHP   = wsp + 128;    // 16: HP, interleaved per column (hp0,hp1)
    float* sWm   = wsp + 144;    // 16: W, interleaved per column (w0,w1)
    float* sC    = wsp + 160;    // 16: C rows, (c0,c1) per row
    float* sMean = wsp + 176;    //  8: predicted mean

    // Loop-invariant constants
    const float R00 = gR[0], R01 = gR[1], R10 = gR[2], R11 = gR[3];
    float Qa[8], Qb[8];
#pragma unroll
    for (int k = 0; k < 8; ++k) { Qa[k] = gQ[a * 8 + k]; Qb[k] = gQ[(a + 1) * 8 + k]; }

    float* omb = oMean + (size_t)b * Tt * 8;
    float* ocb = oCov  + (size_t)b * Tt * 64;

    // ---- init state + t=0 outputs ----
    float pra[8], prb[8];   // own two rows of P (registers)
    {
        const float4 c0 = *(const float4*)(gCov0 + a * 8);
        const float4 c1 = *(const float4*)(gCov0 + a * 8 + 4);
        const float4 c2 = *(const float4*)(gCov0 + a * 8 + 8);
        const float4 c3 = *(const float4*)(gCov0 + a * 8 + 12);
        pra[0]=c0.x; pra[1]=c0.y; pra[2]=c0.z; pra[3]=c0.w;
        pra[4]=c1.x; pra[5]=c1.y; pra[6]=c1.z; pra[7]=c1.w;
        prb[0]=c2.x; prb[1]=c2.y; prb[2]=c2.z; prb[3]=c2.w;
        prb[4]=c3.x; prb[5]=c3.y; prb[6]=c3.z; prb[7]=c3.w;
        *(float4*)(sP + a * 8)      = c0;
        *(float4*)(sP + a * 8 + 4)  = c1;
        *(float4*)(sP + a * 8 + 8)  = c2;
        *(float4*)(sP + a * 8 + 12) = c3;
        float* oc0 = ocb + a * 8;
        *(float4*)(oc0)      = c0;
        *(float4*)(oc0 + 4)  = c1;
        *(float4*)(oc0 + 8)  = c2;
        *(float4*)(oc0 + 12) = c3;
    }
    {
        const float2 m0 = *(const float2*)(gMean0 + b * 8 + a);
        *(float2*)(sMean + a) = m0;
        *(float2*)(omb + a)   = m0;
    }

    const float* Fb = gF + (size_t)b * Tt * 64;
    const float* Hb = gH + (size_t)b * Tt * 16;
    const float* yb = gy + (size_t)b * Tt * 2;

    // ---- prefetch step 0 inputs ----
    float4 f0 = *(const float4*)(Fb + a * 8);
    float4 f1 = *(const float4*)(Fb + a * 8 + 4);
    float4 f2 = *(const float4*)(Fb + a * 8 + 8);
    float4 f3 = *(const float4*)(Fb + a * 8 + 12);
    float4 h0 = *(const float4*)(Hb);
    float4 h1 = *(const float4*)(Hb + 4);
    float4 h2 = *(const float4*)(Hb + 8);
    float4 h3 = *(const float4*)(Hb + 12);
    float2 yv = *(const float2*)(yb);

    __syncwarp();

    for (int t = 0; t < Tt - 1; ++t) {
        // current-step operands (copies free the prefetch registers)
        const float fra[8] = {f0.x, f0.y, f0.z, f0.w, f1.x, f1.y, f1.z, f1.w};
        const float frb[8] = {f2.x, f2.y, f2.z, f2.w, f3.x, f3.y, f3.z, f3.w};
        const float ha[8]  = {h0.x, h0.y, h0.z, h0.w, h1.x, h1.y, h1.z, h1.w};
        const float hc[8]  = {h2.x, h2.y, h2.z, h2.w, h3.x, h3.y, h3.z, h3.w};
        const float y0 = yv.x, y1 = yv.y;

        // prefetch next step (t+1 <= T-1 always valid)
        {
            const float* Fn = Fb + (size_t)(t + 1) * 64;
            f0 = *(const float4*)(Fn + a * 8);
            f1 = *(const float4*)(Fn + a * 8 + 4);
            f2 = *(const float4*)(Fn + a * 8 + 8);
            f3 = *(const float4*)(Fn + a * 8 + 12);
            const float* Hn = Hb + (size_t)(t + 1) * 16;
            h0 = *(const float4*)(Hn);
            h1 = *(const float4*)(Hn + 4);
            h2 = *(const float4*)(Hn + 8);
            h3 = *(const float4*)(Hn + 12);
            yv = *(const float2*)(yb + (size_t)(t + 1) * 2);
        }

        // ---- HP columns a, a+1 from own register rows (P symmetric) ----
        float hpa0 = 0.f, hpa1 = 0.f, hpb0 = 0.f, hpb1 = 0.f;
#pragma unroll
        for (int s = 0; s < 8; ++s) {
            hpa0 += ha[s] * pra[s];
            hpa1 += hc[s] * pra[s];
            hpb0 += ha[s] * prb[s];
            hpb1 += hc[s] * prb[s];
        }
        *(float4*)(sHP + 2 * a) = make_float4(hpa0, hpa1, hpb0, hpb1);
        __syncwarp();  // sync A: sHP visible

        // ---- full HP + mean (broadcast reads) ----
        float HP0[8], HP1[8], mn[8];
        {
            float4 v = *(const float4*)(sHP);
            HP0[0]=v.x; HP1[0]=v.y; HP0[1]=v.z; HP1[1]=v.w;
            v = *(const float4*)(sHP + 4);
            HP0[2]=v.x; HP1[2]=v.y; HP0[3]=v.z; HP1[3]=v.w;
            v = *(const float4*)(sHP + 8);
            HP0[4]=v.x; HP1[4]=v.y; HP0[5]=v.z; HP1[5]=v.w;
            v = *(const float4*)(sHP + 12);
            HP0[6]=v.x; HP1[6]=v.y; HP0[7]=v.z; HP1[7]=v.w;
            const float4 m0 = *(const float4*)(sMean);
            const float4 m1 = *(const float4*)(sMean + 4);
            mn[0]=m0.x; mn[1]=m0.y; mn[2]=m0.z; mn[3]=m0.w;
            mn[4]=m1.x; mn[5]=m1.y; mn[6]=m1.z; mn[7]=m1.w;
        }

        // ---- Smat = HP H^T + R (both off-diagonals, like reference) + resid ----
        float s00 = R00, s01 = R01, s10 = R10, s11 = R11;
        float r0 = y0, r1 = y1;
#pragma unroll
        for (int k = 0; k < 8; ++k) {
            s00 += HP0[k] * ha[k];
            s01 += HP0[k] * hc[k];
            s10 += HP1[k] * ha[k];
            s11 += HP1[k] * hc[k];
            r0  -= ha[k] * mn[k];
            r1  -= hc[k] * mn[k];
        }
        const float inv = 1.0f / (s00 * s11 - s01 * s10);

        // W = S^{-1} HP, own columns a, a+1
        const float w0a = inv * ( s11 * hpa0 - s01 * hpa1);
        const float w1a = inv * (-s10 * hpa0 + s00 * hpa1);
        const float w0b = inv * ( s11 * hpb0 - s01 * hpb1);
        const float w1b = inv * (-s10 * hpb0 + s00 * hpb1);
        *(float4*)(sWm + 2 * a) = make_float4(w0a, w1a, w0b, w1b);
        __syncwarp();  // sync B: sW visible; all sMean reads done

        // ---- C rows a, a+1 = F_row @ K ----
        float c0a = 0.f, c1a = 0.f, c0b = 0.f, c1b = 0.f;
        {
            float w0[8], w1[8];
            float4 v = *(const float4*)(sWm);
            w0[0]=v.x; w1[0]=v.y; w0[1]=v.z; w1[1]=v.w;
            v = *(const float4*)(sWm + 4);
            w0[2]=v.x; w1[2]=v.y; w0[3]=v.z; w1[3]=v.w;
            v = *(const float4*)(sWm + 8);
            w0[4]=v.x; w1[4]=v.y; w0[5]=v.z; w1[5]=v.w;
            v = *(const float4*)(sWm + 12);
            w0[6]=v.x; w1[6]=v.y; w0[7]=v.z; w1[7]=v.w;
#pragma unroll
            for (int j = 0; j < 8; ++j) {
                c0a += fra[j] * w0[j];
                c1a += fra[j] * w1[j];
                c0b += frb[j] * w0[j];
                c1b += frb[j] * w1[j];
            }
        }

        // ---- Z rows a, a+1 (registers) ----
        float z0[8], z1[8];
#pragma unroll
        for (int k = 0; k < 8; ++k) {
            z0[k] = fra[k] - c0a * ha[k] - c1a * hc[k];
            z1[k] = frb[k] - c0b * ha[k] - c1b * hc[k];
        }
        *(float4*)(sZ + a * 8)      = make_float4(z0[0], z0[1], z0[2], z0[3]);
        *(float4*)(sZ + a * 8 + 4)  = make_float4(z0[4], z0[5], z0[6], z0[7]);
        *(float4*)(sZ + a * 8 + 8)  = make_float4(z1[0], z1[1], z1[2], z1[3]);
        *(float4*)(sZ + a * 8 + 12) = make_float4(z1[4], z1[5], z1[6], z1[7]);
        *(float4*)(sC + 2 * a)      = make_float4(c0a, c1a, c0b, c1b);

        // ---- predicted means ----
        float mpa = c0a * r0 + c1a * r1;
        float mpb = c0b * r0 + c1b * r1;
#pragma unroll
        for (int j = 0; j < 8; ++j) {
            mpa += fra[j] * mn[j];
            mpb += frb[j] * mn[j];
        }

        // ---- matmul 1: acc{0,1} = z{0,1} @ P (one pass over broadcast P rows) ----
        float acc0[8] = {0,0,0,0,0,0,0,0};
        float acc1[8] = {0,0,0,0,0,0,0,0};
#pragma unroll
        for (int j = 0; j < 8; ++j) {
            const float4 p0 = *(const float4*)(sP + j * 8);
            const float4 p1 = *(const float4*)(sP + j * 8 + 4);
            const float u = z0[j], w = z1[j];
            acc0[0] += u * p0.x; acc0[1] += u * p0.y;
            acc0[2] += u * p0.z; acc0[3] += u * p0.w;
            acc0[4] += u * p1.x; acc0[5] += u * p1.y;
            acc0[6] += u * p1.z; acc0[7] += u * p1.w;
            acc1[0] += w * p0.x; acc1[1] += w * p0.y;
            acc1[2] += w * p0.z; acc1[3] += w * p0.w;
            acc1[4] += w * p1.x; acc1[5] += w * p1.y;
            acc1[6] += w * p1.z; acc1[7] += w * p1.w;
        }
        __syncwarp();  // sync C: sZ, sC visible; all old-sP reads complete

        // ---- CRC^T coefficients + C rows ----
        const float v0a = R00 * c0a + R10 * c1a;
        const float v1a = R01 * c0a + R11 * c1a;
        const float v0b = R00 * c0b + R10 * c1b;
        const float v1b = R01 * c0b + R11 * c1b;
        float cp0[8], cp1[8];
        {
            float4 v = *(const float4*)(sC);
            cp0[0]=v.x; cp1[0]=v.y; cp0[1]=v.z; cp1[1]=v.w;
            v = *(const float4*)(sC + 4);
            cp0[2]=v.x; cp1[2]=v.y; cp0[3]=v.z; cp1[3]=v.w;
            v = *(const float4*)(sC + 8);
            cp0[4]=v.x; cp1[4]=v.y; cp0[5]=v.z; cp1[5]=v.w;
            v = *(const float4*)(sC + 12);
            cp0[6]=v.x; cp1[6]=v.y; cp0[7]=v.z; cp1[7]=v.w;
        }

        // ---- matmul 2: P' rows a,a+1 = acc @ Z^T + v.C^T + Q (one Z pass) ----
        float pn0[8], pn1[8];
#pragma unroll
        for (int k = 0; k < 8; ++k) {
            const float4 q0 = *(const float4*)(sZ + k * 8);
            const float4 q1 = *(const float4*)(sZ + k * 8 + 4);
            float ta = Qa[k] + v0a * cp0[k] + v1a * cp1[k];
            float tb = Qb[k] + v0b * cp0[k] + v1b * cp1[k];
            ta += acc0[0]*q0.x + acc0[1]*q0.y + acc0[2]*q0.z + acc0[3]*q0.w
                + acc0[4]*q1.x + acc0[5]*q1.y + acc0[6]*q1.z + acc0[7]*q1.w;
            tb += acc1[0]*q0.x + acc1[1]*q0.y + acc1[2]*q0.z + acc1[3]*q0.w
                + acc1[4]*q1.x + acc1[5]*q1.y + acc1[6]*q1.z + acc1[7]*q1.w;
            pn0[k] = ta;
            pn1[k] = tb;
        }
#pragma unroll
        for (int k = 0; k < 8; ++k) { pra[k] = pn0[k]; prb[k] = pn1[k]; }

        // ---- commit state + outputs ----
        *(float2*)(sMean + a) = make_float2(mpa, mpb);
        const float4 pl0 = make_float4(pn0[0], pn0[1], pn0[2], pn0[3]);
        const float4 pl1 = make_float4(pn0[4], pn0[5], pn0[6], pn0[7]);
        const float4 pl2 = make_float4(pn1[0], pn1[1], pn1[2], pn1[3]);
        const float4 pl3 = make_float4(pn1[4], pn1[5], pn1[6], pn1[7]);
        *(float4*)(sP + a * 8)      = pl0;
        *(float4*)(sP + a * 8 + 4)  = pl1;
        *(float4*)(sP + a * 8 + 8)  = pl2;
        *(float4*)(sP + a * 8 + 12) = pl3;

        *(float2*)(omb + (size_t)(t + 1) * 8 + a) = make_float2(mpa, mpb);
        float* oc = ocb + (size_t)(t + 1) * 64 + a * 8;
        *(float4*)(oc)      = pl0;
        *(float4*)(oc + 4)  = pl1;
        *(float4*)(oc + 8)  = pl2;
        *(float4*)(oc + 12) = pl3;
        __syncwarp();  // sync D: sP, sMean visible for next iteration
    }
}

extern "C" void kernel_launch(void* const* d_in, const int* in_sizes, int n_in,
                              void* d_out, int out_size)
{
    // metadata order: y, F, H, Q, R, init_mean, init_cov, n_step
    const float* gy     = (const float*)d_in[0];
    const float* gF     = (const float*)d_in[1];
    const float* gH     = (const float*)d_in[2];
    const float* gQ     = (const float*)d_in[3];
    const float* gR     = (const float*)d_in[4];
    const float* gMean0 = (const float*)d_in[5];
    const float* gCov0  = (const float*)d_in[6];
    (void)in_sizes; (void)n_in;

    float* oMean = (float*)d_out;                          // [B,T,8]
    float* oCov  = (float*)d_out + (size_t)Bb * Tt * 8;    // [B,T,8,8]
    (void)out_size;

    kalman_kernel<<<Bb / BPW, 32>>>(gy, gF, gH, gQ, gR, gMean0, gCov0,
                                    oMean, oCov);
}

// round 9
// speedup vs baseline: 1.2163x; 1.2163x over previous
#include <cuda_runtime.h>

// Kalman filter, simple-form (non-Joseph) covariance update, fused predict.
// B=4096, T=200, S=8, M=2. 8 threads per batch (thread = state row),
// 4 batches per 32-thread block, 1024 blocks (~7 warps/SM: latency is hidden).
//
// Per step (mathematically identical to Joseph form for the exact gain):
//   HP   = H P                      (own register row of P; P symmetric)
//   S    = HP H^T + R ; W = S^{-1} HP ; K = W^T  (thread needs only own K row)
//   P_u  = P - K^T (HP)             (register row; no W/C broadcast needed)
//   mu   = mean + K resid
//   mean'= F mu
//   P'   = F P_u F^T + Q            (two broadcast matmuls: sPU rows, sF rows)
// P itself never lives in SMEM; only P_u and F do. 3 syncwarps per step.

namespace {
constexpr int Bb  = 4096;
constexpr int Tt  = 200;
constexpr int BPB = 4;     // batches per block (one warp)
constexpr int WSF = 168;   // workspace stride (mod 32 == 8, 16B-aligned)
}

__global__ __launch_bounds__(32)
void kalman_kernel(const float* __restrict__ gy,      // [B,T,2]
                   const float* __restrict__ gF,      // [B,T,8,8]
                   const float* __restrict__ gH,      // [B,T,2,8]
                   const float* __restrict__ gQ,      // [8,8]
                   const float* __restrict__ gR,      // [2,2]
                   const float* __restrict__ gMean0,  // [B,8]
                   const float* __restrict__ gCov0,   // [8,8]
                   float* __restrict__ oMean,         // [B,T,8]
                   float* __restrict__ oCov)          // [B,T,8,8]
{
    __shared__ __align__(16) float sw[BPB * WSF];
    const int tid = threadIdx.x;
    const int lb  = tid >> 3;   // local batch
    const int i   = tid & 7;    // state row owned by this thread
    const int b   = blockIdx.x * BPB + lb;

    float* wsp   = sw + lb * WSF;
    float* sPU   = wsp;          // 64: updated covariance P_u
    float* sF    = wsp + 64;     // 64: F_t
    float* sHP   = wsp + 128;    // 16: HP columns, interleaved (hp0,hp1) per i
    float* sMU   = wsp + 144;    //  8: updated mean
    float* sMean = wsp + 152;    //  8: predicted mean

    // Loop-invariant constants
    const float R00 = gR[0], R01 = gR[1], R10 = gR[2], R11 = gR[3];
    float Qr[8];
#pragma unroll
    for (int k = 0; k < 8; ++k) Qr[k] = gQ[i * 8 + k];

    float* omb = oMean + (size_t)b * Tt * 8;
    float* ocb = oCov  + (size_t)b * Tt * 64;

    // ---- init state + t=0 outputs ----
    float pr[8];  // own row of P (registers only; P never in SMEM)
    {
        const float4 ic0 = *(const float4*)(gCov0 + i * 8);
        const float4 ic1 = *(const float4*)(gCov0 + i * 8 + 4);
        pr[0]=ic0.x; pr[1]=ic0.y; pr[2]=ic0.z; pr[3]=ic0.w;
        pr[4]=ic1.x; pr[5]=ic1.y; pr[6]=ic1.z; pr[7]=ic1.w;
        *(float4*)(ocb + i * 8)     = ic0;
        *(float4*)(ocb + i * 8 + 4) = ic1;
    }
    const float m0i = gMean0[b * 8 + i];
    sMean[i] = m0i;
    omb[i] = m0i;

    const float* Fb = gF + (size_t)b * Tt * 64;
    const float* Hb = gH + (size_t)b * Tt * 16;
    const float* yb = gy + (size_t)b * Tt * 2;

    // ---- prefetch step 0 inputs ----
    float4 f0 = *(const float4*)(Fb + i * 8);
    float4 f1 = *(const float4*)(Fb + i * 8 + 4);
    float4 h0 = *(const float4*)(Hb);
    float4 h1 = *(const float4*)(Hb + 4);
    float4 h2 = *(const float4*)(Hb + 8);
    float4 h3 = *(const float4*)(Hb + 12);
    float2 yv = *(const float2*)(yb);

    __syncwarp();

    for (int t = 0; t < Tt - 1; ++t) {
        // current-step operands (copies free the prefetch registers)
        const float fr[8] = {f0.x, f0.y, f0.z, f0.w, f1.x, f1.y, f1.z, f1.w};
        const float ha[8] = {h0.x, h0.y, h0.z, h0.w, h1.x, h1.y, h1.z, h1.w};
        const float hc[8] = {h2.x, h2.y, h2.z, h2.w, h3.x, h3.y, h3.z, h3.w};
        const float y0 = yv.x, y1 = yv.y;

        // prefetch next step (t+1 <= T-1 always valid)
        {
            const float* Fn = Fb + (size_t)(t + 1) * 64;
            f0 = *(const float4*)(Fn + i * 8);
            f1 = *(const float4*)(Fn + i * 8 + 4);
            const float* Hn = Hb + (size_t)(t + 1) * 16;
            h0 = *(const float4*)(Hn);
            h1 = *(const float4*)(Hn + 4);
            h2 = *(const float4*)(Hn + 8);
            h3 = *(const float4*)(Hn + 12);
            yv = *(const float2*)(yb + (size_t)(t + 1) * 2);
        }

        // ---- phase 1: F row to SMEM; HP column i from own P row (P symm) ----
        *(float4*)(sF + i * 8)     = make_float4(fr[0], fr[1], fr[2], fr[3]);
        *(float4*)(sF + i * 8 + 4) = make_float4(fr[4], fr[5], fr[6], fr[7]);
        float hp0 = 0.f, hp1 = 0.f;
#pragma unroll
        for (int s = 0; s < 8; ++s) {
            hp0 += ha[s] * pr[s];
            hp1 += hc[s] * pr[s];
        }
        *(float2*)(sHP + 2 * i) = make_float2(hp0, hp1);
        __syncwarp();  // sync A: sHP, sF visible

        // ---- phase 2: innovation, gain, P_u row, mean_u element ----
        float HP0[8], HP1[8], mn[8];
        {
            float4 v = *(const float4*)(sHP);
            HP0[0]=v.x; HP1[0]=v.y; HP0[1]=v.z; HP1[1]=v.w;
            v = *(const float4*)(sHP + 4);
            HP0[2]=v.x; HP1[2]=v.y; HP0[3]=v.z; HP1[3]=v.w;
            v = *(const float4*)(sHP + 8);
            HP0[4]=v.x; HP1[4]=v.y; HP0[5]=v.z; HP1[5]=v.w;
            v = *(const float4*)(sHP + 12);
            HP0[6]=v.x; HP1[6]=v.y; HP0[7]=v.z; HP1[7]=v.w;
            const float4 m0 = *(const float4*)(sMean);
            const float4 m1 = *(const float4*)(sMean + 4);
            mn[0]=m0.x; mn[1]=m0.y; mn[2]=m0.z; mn[3]=m0.w;
            mn[4]=m1.x; mn[5]=m1.y; mn[6]=m1.z; mn[7]=m1.w;
        }

        float s00 = R00, s01 = R01, s10 = R10, s11 = R11;
        float r0 = y0, r1 = y1;
#pragma unroll
        for (int k = 0; k < 8; ++k) {
            s00 += HP0[k] * ha[k];
            s01 += HP0[k] * hc[k];
            s10 += HP1[k] * ha[k];
            s11 += HP1[k] * hc[k];
            r0  -= ha[k] * mn[k];
            r1  -= hc[k] * mn[k];
        }
        const float inv = 1.0f / (s00 * s11 - s01 * s10);

        // K row i = (w0i, w1i)   (W = S^{-1} HP, K = W^T)
        const float w0i = inv * ( s11 * hp0 - s01 * hp1);
        const float w1i = inv * (-s10 * hp0 + s00 * hp1);

        // P_u row i = P row i - w0i*HP0 - w1i*HP1  (registers -> SMEM)
        float pu[8];
#pragma unroll
        for (int k = 0; k < 8; ++k)
            pu[k] = pr[k] - w0i * HP0[k] - w1i * HP1[k];
        *(float4*)(sPU + i * 8)     = make_float4(pu[0], pu[1], pu[2], pu[3]);
        *(float4*)(sPU + i * 8 + 4) = make_float4(pu[4], pu[5], pu[6], pu[7]);

        // mean_u element i
        sMU[i] = mn[i] + w0i * r0 + w1i * r1;
        __syncwarp();  // sync B: sPU, sMU visible; all sMean reads done

        // ---- phase 3: predict ----
        // mean_p row i = F_row_i @ mu
        float mp = 0.f;
        {
            const float4 a = *(const float4*)(sMU);
            const float4 c = *(const float4*)(sMU + 4);
            mp = fr[0]*a.x + fr[1]*a.y + fr[2]*a.z + fr[3]*a.w
               + fr[4]*c.x + fr[5]*c.y + fr[6]*c.z + fr[7]*c.w;
        }

        // G = F_row_i @ P_u  (broadcast rows of sPU)
        float g[8] = {0, 0, 0, 0, 0, 0, 0, 0};
#pragma unroll
        for (int j = 0; j < 8; ++j) {
            const float4 p0 = *(const float4*)(sPU + j * 8);
            const float4 p1 = *(const float4*)(sPU + j * 8 + 4);
            const float c = fr[j];
            g[0] += c * p0.x; g[1] += c * p0.y;
            g[2] += c * p0.z; g[3] += c * p0.w;
            g[4] += c * p1.x; g[5] += c * p1.y;
            g[6] += c * p1.z; g[7] += c * p1.w;
        }

        // P' row i = G @ F^T + Q  (broadcast rows of sF)
        float pn[8];
#pragma unroll
        for (int k = 0; k < 8; ++k) {
            const float4 q0 = *(const float4*)(sF + k * 8);
            const float4 q1 = *(const float4*)(sF + k * 8 + 4);
            pn[k] = Qr[k]
                  + g[0] * q0.x + g[1] * q0.y + g[2] * q0.z + g[3] * q0.w
                  + g[4] * q1.x + g[5] * q1.y + g[6] * q1.z + g[7] * q1.w;
        }
#pragma unroll
        for (int k = 0; k < 8; ++k) pr[k] = pn[k];

        // commit state + outputs
        sMean[i] = mp;  // safe: all old-sMean reads happened before sync B
        const float4 pnl = make_float4(pn[0], pn[1], pn[2], pn[3]);
        const float4 pnh = make_float4(pn[4], pn[5], pn[6], pn[7]);
        omb[(size_t)(t + 1) * 8 + i] = mp;
        float* oc = ocb + (size_t)(t + 1) * 64 + i * 8;
        *(float4*)(oc)     = pnl;
        *(float4*)(oc + 4) = pnh;
        __syncwarp();  // sync C: sPU/sF reads done; sMean visible for next iter
    }
}

extern "C" void kernel_launch(void* const* d_in, const int* in_sizes, int n_in,
                              void* d_out, int out_size)
{
    // metadata order: y, F, H, Q, R, init_mean, init_cov, n_step
    const float* gy     = (const float*)d_in[0];
    const float* gF     = (const float*)d_in[1];
    const float* gH     = (const float*)d_in[2];
    const float* gQ     = (const float*)d_in[3];
    const float* gR     = (const float*)d_in[4];
    const float* gMean0 = (const float*)d_in[5];
    const float* gCov0  = (const float*)d_in[6];
    (void)in_sizes; (void)n_in;

    float* oMean = (float*)d_out;                          // [B,T,8]
    float* oCov  = (float*)d_out + (size_t)Bb * Tt * 8;    // [B,T,8,8]
    (void)out_size;

    kalman_kernel<<<Bb / BPB, BPB * 8>>>(gy, gF, gH, gQ, gR, gMean0, gCov0,
                                         oMean, oCov);
}